// round 1
// baseline (speedup 1.0000x reference)
#include <cuda_runtime.h>
#include <cstdint>

#define N_VOX   131072
#define KVOL    27
#define P_PAIRS 65536
#define CIN     64
#define COUT    64

#define TILE_P       128
#define TPB_TILES    4
#define THREADS      256
#define BLOCKS_PER_K ((P_PAIRS / TILE_P) / TPB_TILES)   // 128

typedef unsigned long long ull;

// ---- packed f32x2 helpers (ptxas will not auto-fuse FFMA2; must come from PTX) ----
__device__ __forceinline__ ull pack_dup(float x) {
    ull r;
    asm("mov.b64 %0, {%1, %1};" : "=l"(r) : "f"(x));
    return r;
}
__device__ __forceinline__ void fma2(ull& d, ull a, ull b) {
    asm("fma.rn.f32x2 %0, %1, %2, %0;" : "+l"(d) : "l"(a), "l"(b));
}
__device__ __forceinline__ void unpack2(ull v, float& a, float& b) {
    asm("mov.b64 {%0, %1}, %2;" : "=f"(a), "=f"(b) : "l"(v));
}
// 16B vector reduction: one L2 sector-level RMW per 32B instead of per-lane scalar REDs
__device__ __forceinline__ void red_add_v4(float* addr, ull ab, ull cd) {
    float a, b, c, d;
    unpack2(ab, a, b);
    unpack2(cd, c, d);
    asm volatile("red.global.add.v4.f32 [%0], {%1, %2, %3, %4};"
                 :: "l"(addr), "f"(a), "f"(b), "f"(c), "f"(d) : "memory");
}

// out[n][c] = bias[c]  (d_out is poisoned to 0xAA; must initialize before scatter)
__global__ void init_bias_kernel(float* __restrict__ out, const float* __restrict__ bias) {
    int idx = blockIdx.x * blockDim.x + threadIdx.x;      // one float4 per thread
    int c4  = idx & (COUT / 4 - 1);                       // 16 float4 per output row
    float4 b = reinterpret_cast<const float4*>(bias)[c4];
    reinterpret_cast<float4*>(out)[idx] = b;
}

// Per kernel-offset: gather -> 128x64x64 fp32 GEMM (f32x2 packed) -> vector scatter-add
__global__ void __launch_bounds__(THREADS, 2)
conv_scatter_kernel(const float* __restrict__ in_feats,
                    const float* __restrict__ W,
                    const int*   __restrict__ imap,
                    const int*   __restrict__ omap,
                    float*       __restrict__ out)
{
    __shared__ float sW[CIN][COUT];        // 16 KB  W[k][ci][co]
    __shared__ float sX[CIN][TILE_P];      // 32 KB  gathered, transposed
    __shared__ int   sO[TILE_P];

    const int k   = blockIdx.x / BLOCKS_PER_K;
    const int bk  = blockIdx.x % BLOCKS_PER_K;
    const int tid = threadIdx.x;

    // Stage W[k] once per block
    const float4* Wk = reinterpret_cast<const float4*>(W + k * CIN * COUT);
    #pragma unroll
    for (int i = tid; i < CIN * COUT / 4; i += THREADS)
        reinterpret_cast<float4*>(sW)[i] = Wk[i];

    const int tp = tid >> 3;   // 0..31 : pair-tile row (4 pairs each)
    const int tc = tid & 7;    // 0..7  : cout column (couts tc*4..+3 and 32+tc*4..+3)
    const int gp = tid >> 1;   // gather: pair index
    const int gh = tid & 1;    // gather: channel half

    for (int t = 0; t < TPB_TILES; ++t) {
        const int pbase = (bk * TPB_TILES + t) * TILE_P;
        const int* im = imap + k * P_PAIRS + pbase;
        const int* om = omap + k * P_PAIRS + pbase;

        __syncthreads();   // protects sX/sO reuse across tiles; covers sW on t==0

        // Gather 128 rows x 64 ch, store transposed so compute reads conflict-free LDS.128
        {
            const int row = im[gp];
            const float4* src = reinterpret_cast<const float4*>(
                in_feats + (size_t)row * CIN + gh * 32);
            #pragma unroll
            for (int q = 0; q < 8; ++q) {
                float4 v = src[q];
                int ci = gh * 32 + q * 4;
                sX[ci + 0][gp] = v.x;
                sX[ci + 1][gp] = v.y;
                sX[ci + 2][gp] = v.z;
                sX[ci + 3][gp] = v.w;
            }
            if (tid < TILE_P) sO[tid] = om[tid];
        }
        __syncthreads();

        // Register GEMM: 4 pairs x 8 couts per thread, f32x2 accumulators
        ull acc[4][4];
        #pragma unroll
        for (int i = 0; i < 4; ++i)
            #pragma unroll
            for (int j = 0; j < 4; ++j) acc[i][j] = 0ull;

        #pragma unroll 4
        for (int ci = 0; ci < CIN; ++ci) {
            float4 xv = *reinterpret_cast<const float4*>(&sX[ci][tp * 4]);
            // couts tc*4..tc*4+3 (banks 4tc..4tc+3: conflict-free across tc=0..7)
            ulonglong2 wa = *reinterpret_cast<const ulonglong2*>(&sW[ci][tc * 4]);
            ulonglong2 wb = *reinterpret_cast<const ulonglong2*>(&sW[ci][32 + tc * 4]);
            ull x0 = pack_dup(xv.x), x1 = pack_dup(xv.y);
            ull x2 = pack_dup(xv.z), x3 = pack_dup(xv.w);
            fma2(acc[0][0], x0, wa.x); fma2(acc[0][1], x0, wa.y);
            fma2(acc[0][2], x0, wb.x); fma2(acc[0][3], x0, wb.y);
            fma2(acc[1][0], x1, wa.x); fma2(acc[1][1], x1, wa.y);
            fma2(acc[1][2], x1, wb.x); fma2(acc[1][3], x1, wb.y);
            fma2(acc[2][0], x2, wa.x); fma2(acc[2][1], x2, wa.y);
            fma2(acc[2][2], x2, wb.x); fma2(acc[2][3], x2, wb.y);
            fma2(acc[3][0], x3, wa.x); fma2(acc[3][1], x3, wa.y);
            fma2(acc[3][2], x3, wb.x); fma2(acc[3][3], x3, wb.y);
        }

        // Scatter-add: 16B-aligned vector REDs, channels contiguous per thread
        #pragma unroll
        for (int pr = 0; pr < 4; ++pr) {
            int orow = sO[tp * 4 + pr];
            float* dst = out + (size_t)orow * COUT + tc * 4;
            red_add_v4(dst,      acc[pr][0], acc[pr][1]);
            red_add_v4(dst + 32, acc[pr][2], acc[pr][3]);
        }
    }
}

extern "C" void kernel_launch(void* const* d_in, const int* in_sizes, int n_in,
                              void* d_out, int out_size) {
    const float* in_feats = (const float*)d_in[0];   // [N, CIN] f32
    const float* kernel   = (const float*)d_in[1];   // [KVOL, CIN, COUT] f32
    const float* bias     = (const float*)d_in[2];   // [COUT] f32
    const int*   imap     = (const int*)d_in[3];     // [KVOL, P] i32
    const int*   omap     = (const int*)d_in[4];     // [KVOL, P] i32
    float* out = (float*)d_out;                      // [N, COUT] f32

    init_bias_kernel<<<(N_VOX * COUT / 4) / 256, 256>>>(out, bias);
    conv_scatter_kernel<<<KVOL * BLOCKS_PER_K, THREADS>>>(in_feats, kernel, imap, omap, out);
}

// round 5
// speedup vs baseline: 1.2447x; 1.2447x over previous
#include <cuda_runtime.h>
#include <cstdint>

#define N_VOX   131072
#define KVOL    27
#define P_PAIRS 65536
#define CIN     64
#define COUT    64
#define TILE_P  128
#define NT_K    (P_PAIRS / TILE_P)          // 512 tiles per kernel offset
#define NT_TOTAL (KVOL * NT_K)              // 13824 tiles
#define GRID    576                         // ~4 CTAs/SM, single wave (592 slots)
#define CHUNK   (NT_TOTAL / GRID)           // 24 tiles per CTA, exact cover
#define THREADS 256

// ---- arch gate: tcgen05 exists only on the arch-specific (sm_103a) pass ----
#if defined(__CUDA_ARCH__) && (__CUDA_ARCH__ >= 1000) && \
    (defined(__CUDA_ARCH_FEAT_SM103_ALL) || defined(__CUDA_ARCH_FEAT_SM100_ALL) || \
     defined(__CUDA_ARCH_SPECIFIC__))
#define TC_PATH 1
#else
#define TC_PATH 0
#endif

// idesc, kind::tf32: dtype=F32(1)<<4, atype=TF32(2)<<7, btype=TF32(2)<<10,
// N>>3 @bit17, M>>4 @bit24  (field layout verified against test_mma's 0x8080490)
#define IDESC_TF32 ((1u<<4) | (2u<<7) | (2u<<10) | ((COUT/8)<<17) | ((TILE_P/16)<<24))

// dynamic SMEM layout (offsets from 1024-aligned base)
#define OFF_A    0        // A: 128x64 tf32, blocked SW128 atoms (32 KB)
#define OFF_B    32768    // B: Wt[k] 64x64 tf32, blocked SW128 (16 KB)
#define OFF_O    49152    // sO[128]
#define OFF_MBAR 49664
#define OFF_TPTR 49680
#define SMEM_DYN 50688    // incl. alignment slack

#define TMEM_COLS 64

__device__ float g_Wt[KVOL * CIN * COUT];   // W transposed to [k][co][ci], tf32-rounded

typedef unsigned long long ull;

// ---------- base-arch helpers ----------
static __device__ __forceinline__ uint32_t cvta_smem(const void* p) {
    uint32_t a;
    asm("{ .reg .u64 t; cvta.to.shared.u64 t, %1; cvt.u32.u64 %0, t; }" : "=r"(a) : "l"(p));
    return a;
}
static __device__ __forceinline__ uint32_t tf32_rna(float x) {
    uint32_t r; asm("cvt.rna.tf32.f32 %0, %1;" : "=r"(r) : "f"(x)); return r;
}
static __device__ __forceinline__ void sts128(uint32_t a, uint32_t x, uint32_t y,
                                              uint32_t z, uint32_t w) {
    asm volatile("st.shared.v4.b32 [%0], {%1,%2,%3,%4};"
                 :: "r"(a), "r"(x), "r"(y), "r"(z), "r"(w) : "memory");
}
static __device__ __forceinline__ ull pack_dup(float x) {
    ull r; asm("mov.b64 %0, {%1, %1};" : "=l"(r) : "f"(x)); return r;
}
static __device__ __forceinline__ void fma2(ull& d, ull a, ull b) {
    asm("fma.rn.f32x2 %0, %1, %2, %0;" : "+l"(d) : "l"(a), "l"(b));
}
static __device__ __forceinline__ void red4(float* addr, float a, float b, float c, float d) {
    asm volatile("red.global.add.v4.f32 [%0], {%1,%2,%3,%4};"
                 :: "l"(addr), "f"(a), "f"(b), "f"(c), "f"(d) : "memory");
}
static __device__ __forceinline__ void red4p(float* addr, ull ab, ull cd) {
    float a, b, c, d;
    asm("mov.b64 {%0, %1}, %2;" : "=f"(a), "=f"(b) : "l"(ab));
    asm("mov.b64 {%0, %1}, %2;" : "=f"(c), "=f"(d) : "l"(cd));
    red4(addr, a, b, c, d);
}

#if TC_PATH
// ---------- sm_103a-only helpers ----------
static __device__ __forceinline__ bool elect_one() {
    uint32_t p;
    asm volatile("{ .reg .pred p; elect.sync _|p, 0xFFFFFFFF; selp.b32 %0, 1, 0, p; }" : "=r"(p));
    return p != 0;
}
static __device__ __forceinline__ uint64_t make_desc(uint32_t addr) {
    // SW128 (layout=2), version=1 (Blackwell), SBO=64, LBO=1
    return 0x4000404000010000ull | (uint64_t)((addr >> 4) & 0x3FFF);
}
static __device__ __forceinline__ void mbar_init(uint32_t mbar, uint32_t cnt) {
    asm volatile("mbarrier.init.shared.b64 [%0], %1;" :: "r"(mbar), "r"(cnt) : "memory");
}
static __device__ __forceinline__ void mbar_wait(uint32_t mbar, uint32_t phase) {
    uint32_t done;
    asm volatile("{ .reg .pred p;\n"
                 "mbarrier.try_wait.parity.acquire.cta.shared::cta.b64 p, [%1], %2;\n"
                 "selp.b32 %0, 1, 0, p; }"
                 : "=r"(done) : "r"(mbar), "r"(phase) : "memory");
    while (!done) {
        asm volatile("{ .reg .pred p;\n"
                     "mbarrier.try_wait.parity.acquire.cta.shared::cta.b64 p, [%1], %2, 0x989680;\n"
                     "selp.b32 %0, 1, 0, p; }"
                     : "=r"(done) : "r"(mbar), "r"(phase) : "memory");
    }
}
static __device__ __forceinline__ void mma_tf32_ss(uint32_t d_tmem, uint64_t ad, uint64_t bd,
                                                   uint32_t idesc, bool acc) {
    uint32_t en = acc ? 1u : 0u;
    asm volatile("{ .reg .pred p; setp.ne.u32 p, %4, 0;\n"
                 "tcgen05.mma.cta_group::1.kind::tf32 [%0], %1, %2, %3, {%5,%5,%5,%5}, p; }"
                 :: "r"(d_tmem), "l"(ad), "l"(bd), "r"(idesc), "r"(en), "r"(0u) : "memory");
}
static __device__ __forceinline__ void tc_commit(uint32_t mbar) {
    asm volatile("tcgen05.commit.cta_group::1.mbarrier::arrive::one.shared::cluster.b64 [%0];"
                 :: "r"(mbar) : "memory");
}
static __device__ __forceinline__ void ldtm32(uint32_t* r, uint32_t taddr) {
    asm volatile("tcgen05.ld.sync.aligned.32x32b.x32.b32 "
                 "{%0,%1,%2,%3,%4,%5,%6,%7,%8,%9,%10,%11,%12,%13,%14,%15,"
                 "%16,%17,%18,%19,%20,%21,%22,%23,%24,%25,%26,%27,%28,%29,%30,%31}, [%32];"
                 : "=r"(r[0]),  "=r"(r[1]),  "=r"(r[2]),  "=r"(r[3]),
                   "=r"(r[4]),  "=r"(r[5]),  "=r"(r[6]),  "=r"(r[7]),
                   "=r"(r[8]),  "=r"(r[9]),  "=r"(r[10]), "=r"(r[11]),
                   "=r"(r[12]), "=r"(r[13]), "=r"(r[14]), "=r"(r[15]),
                   "=r"(r[16]), "=r"(r[17]), "=r"(r[18]), "=r"(r[19]),
                   "=r"(r[20]), "=r"(r[21]), "=r"(r[22]), "=r"(r[23]),
                   "=r"(r[24]), "=r"(r[25]), "=r"(r[26]), "=r"(r[27]),
                   "=r"(r[28]), "=r"(r[29]), "=r"(r[30]), "=r"(r[31])
                 : "r"(taddr));
}
#endif  // TC_PATH

// ---------- prep: Wt[k][co][ci] = tf32(W[k][ci][co]) ----------
__global__ void prep_wt_kernel(const float* __restrict__ W) {
    int k = blockIdx.x;
    const float* Wk = W + (size_t)k * CIN * COUT;
    float* Dk = g_Wt + (size_t)k * CIN * COUT;
    for (int idx = threadIdx.x; idx < CIN * COUT; idx += blockDim.x) {
        int co = idx >> 6, ci = idx & 63;
        Dk[idx] = __uint_as_float(tf32_rna(Wk[ci * COUT + co]));
    }
}

// ---------- out[n][c] = bias[c] ----------
__global__ void init_bias_kernel(float* __restrict__ out, const float* __restrict__ bias) {
    int idx = blockIdx.x * blockDim.x + threadIdx.x;
    int c4  = idx & (COUT / 4 - 1);
    float4 b = reinterpret_cast<const float4*>(bias)[c4];
    reinterpret_cast<float4*>(out)[idx] = b;
}

// ---------- main ----------
extern __shared__ char dynsmem[];

__global__ void __launch_bounds__(THREADS) __cluster_dims__(1, 1, 1)
conv_main_kernel(const float* __restrict__ in_feats,
                 const float* __restrict__ W,
                 const int*   __restrict__ imap,
                 const int*   __restrict__ omap,
                 float*       __restrict__ out)
{
    const int tid = threadIdx.x;
    const int t0  = blockIdx.x * CHUNK;
    const int t1  = t0 + CHUNK;

#if TC_PATH
    // ======== tcgen05 tf32 path (synchronous per tile; overlap via 4 CTAs/SM) ========
    const uint32_t raw  = cvta_smem(dynsmem);
    const uint32_t base = (raw + 1023u) & ~1023u;
    const int wid  = tid >> 5;
    const int lane = tid & 31;

    if (wid == 0) {
        asm volatile("tcgen05.alloc.cta_group::1.sync.aligned.shared::cta.b32 [%0], %1;"
                     :: "r"(base + OFF_TPTR), "r"((uint32_t)TMEM_COLS) : "memory");
        asm volatile("tcgen05.relinquish_alloc_permit.cta_group::1.sync.aligned;");
    }
    if (tid == 0) mbar_init(base + OFF_MBAR, 1);
    __syncthreads();
    uint32_t tmem;
    asm volatile("ld.shared.b32 %0, [%1];" : "=r"(tmem) : "r"(base + OFF_TPTR));

    // gather geometry: thread handles row p = tid>>1, ci half h = tid&1
    const int p = tid >> 1, h = tid & 1;
    const uint32_t sa_off = ((((uint32_t)(p >> 3)) + h * 16u) << 10) + ((p & 7) << 7);
    const uint32_t sa_xor = (p & 7) << 4;
    int* sO = reinterpret_cast<int*>(dynsmem + (base - raw) + OFF_O);
    const uint64_t adesc = make_desc(base + OFF_A);
    const uint64_t bdesc = make_desc(base + OFF_B);
    const int colhalf = wid >> 2;   // 32-col half of D this warp handles
    const int rowgrp  = wid & 3;    // TMEM subpartition -> output-row group

    int kcur = -1;
    int i = 0;
    for (int t = t0; t < t1; ++t, ++i) {
        const int kk = t >> 9;                 // NT_K == 512
        const int ti = t & (NT_K - 1);

        // stage B = Wt[kk] once per k (prev iteration ended with __syncthreads,
        // and its mbar wait guarantees all prior MMA SMEM reads completed)
        if (kk != kcur) {
            if (tid < 128) {
                int co = tid >> 1, bh = tid & 1;
                const float4* src = reinterpret_cast<const float4*>(
                    g_Wt + (size_t)kk * CIN * COUT + co * CIN + bh * 32);
                uint32_t sb = base + OFF_B +
                              ((((uint32_t)(co >> 3)) + bh * 8u) << 10) + ((co & 7) << 7);
                uint32_t xo = (co & 7) << 4;
                #pragma unroll
                for (int q = 0; q < 8; ++q) {
                    float4 v = src[q];
                    sts128(sb + ((q * 16) ^ xo),
                           __float_as_uint(v.x), __float_as_uint(v.y),
                           __float_as_uint(v.z), __float_as_uint(v.w));
                }
            }
            kcur = kk;
        }

        // ---- gather tile -> sA (tf32, blocked SW128 atoms) ----
        {
            const size_t mo = (size_t)kk * P_PAIRS + (size_t)ti * TILE_P;
            int row = __ldg(imap + mo + p);
            const float4* src = reinterpret_cast<const float4*>(
                in_feats + (size_t)row * CIN + h * 32);
            uint32_t sa = base + OFF_A + sa_off;
            #pragma unroll
            for (int q = 0; q < 8; ++q) {
                float4 v = src[q];
                sts128(sa + ((q * 16) ^ sa_xor),
                       tf32_rna(v.x), tf32_rna(v.y), tf32_rna(v.z), tf32_rna(v.w));
            }
            if (tid < TILE_P) sO[tid] = __ldg(omap + mo + tid);
        }
        asm volatile("fence.proxy.async.shared::cta;" ::: "memory");
        __syncthreads();

        // ---- MMA: 8 k-steps (K=8 each for tf32), single warp, elected thread ----
        if (wid == 0) {
            asm volatile("tcgen05.fence::after_thread_sync;" ::: "memory");
            if (elect_one()) {
                #pragma unroll
                for (int s = 0; s < 8; ++s)
                    mma_tf32_ss(tmem,
                                adesc + (uint64_t)((s >> 2) * 1024 + (s & 3) * 2),
                                bdesc + (uint64_t)((s >> 2) * 512  + (s & 3) * 2),
                                IDESC_TF32, s > 0);
                tc_commit(base + OFF_MBAR);
            }
        }

        // ---- all warps wait MMA, read D, vector scatter-add ----
        mbar_wait(base + OFF_MBAR, (uint32_t)(i & 1));
        asm volatile("tcgen05.fence::after_thread_sync;" ::: "memory");
        uint32_t r[32];
        ldtm32(r, tmem + colhalf * 32);
        asm volatile("tcgen05.wait::ld.sync.aligned;" ::: "memory");
        asm volatile("tcgen05.fence::before_thread_sync;" ::: "memory");

        int orow = sO[rowgrp * 32 + lane];
        float* dst = out + (size_t)orow * COUT + colhalf * 32;
        #pragma unroll
        for (int q = 0; q < 8; ++q)
            red4(dst + q * 4,
                 __uint_as_float(r[4*q+0]), __uint_as_float(r[4*q+1]),
                 __uint_as_float(r[4*q+2]), __uint_as_float(r[4*q+3]));

        __syncthreads();   // D/A/B/sO reuse boundary
    }

    if (wid == 0) {
        asm volatile("tcgen05.dealloc.cta_group::1.sync.aligned.b32 %0, %1;"
                     :: "r"(tmem), "r"((uint32_t)TMEM_COLS));
    }

#else
    // ======== base-arch fallback: f32x2 register GEMM (R1-proven logic) ========
    float* sW = reinterpret_cast<float*>(dynsmem);            // [64][64]
    float* sX = reinterpret_cast<float*>(dynsmem + 16384);    // [64][128]
    int*   sO = reinterpret_cast<int*>(dynsmem + 49152);      // [128]
    const int tp = tid >> 3, tcc = tid & 7, gp = tid >> 1, gh = tid & 1;

    int kcur = -1;
    for (int t = t0; t < t1; ++t) {
        const int kk = t >> 9;
        const int ti = t & (NT_K - 1);
        __syncthreads();
        if (kk != kcur) {
            const float4* Wk = reinterpret_cast<const float4*>(W + (size_t)kk * CIN * COUT);
            for (int idx = tid; idx < CIN * COUT / 4; idx += THREADS)
                reinterpret_cast<float4*>(sW)[idx] = Wk[idx];
            kcur = kk;
        }
        {
            const size_t mo = (size_t)kk * P_PAIRS + (size_t)ti * TILE_P;
            int row = __ldg(imap + mo + gp);
            const float4* src = reinterpret_cast<const float4*>(
                in_feats + (size_t)row * CIN + gh * 32);
            #pragma unroll
            for (int q = 0; q < 8; ++q) {
                float4 v = src[q];
                int ci = gh * 32 + q * 4;
                sX[(ci + 0) * TILE_P + gp] = v.x;
                sX[(ci + 1) * TILE_P + gp] = v.y;
                sX[(ci + 2) * TILE_P + gp] = v.z;
                sX[(ci + 3) * TILE_P + gp] = v.w;
            }
            if (tid < TILE_P) sO[tid] = __ldg(omap + mo + tid);
        }
        __syncthreads();

        ull acc[4][4];
        #pragma unroll
        for (int a = 0; a < 4; ++a)
            #pragma unroll
            for (int c = 0; c < 4; ++c) acc[a][c] = 0ull;

        #pragma unroll 4
        for (int ci = 0; ci < CIN; ++ci) {
            float4 xv = *reinterpret_cast<const float4*>(&sX[ci * TILE_P + tp * 4]);
            ulonglong2 wa = *reinterpret_cast<const ulonglong2*>(&sW[ci * COUT + tcc * 4]);
            ulonglong2 wb = *reinterpret_cast<const ulonglong2*>(&sW[ci * COUT + 32 + tcc * 4]);
            ull x0 = pack_dup(xv.x), x1 = pack_dup(xv.y);
            ull x2 = pack_dup(xv.z), x3 = pack_dup(xv.w);
            fma2(acc[0][0], x0, wa.x); fma2(acc[0][1], x0, wa.y);
            fma2(acc[0][2], x0, wb.x); fma2(acc[0][3], x0, wb.y);
            fma2(acc[1][0], x1, wa.x); fma2(acc[1][1], x1, wa.y);
            fma2(acc[1][2], x1, wb.x); fma2(acc[1][3], x1, wb.y);
            fma2(acc[2][0], x2, wa.x); fma2(acc[2][1], x2, wa.y);
            fma2(acc[2][2], x2, wb.x); fma2(acc[2][3], x2, wb.y);
            fma2(acc[3][0], x3, wa.x); fma2(acc[3][1], x3, wa.y);
            fma2(acc[3][2], x3, wb.x); fma2(acc[3][3], x3, wb.y);
        }

        #pragma unroll
        for (int pr = 0; pr < 4; ++pr) {
            int orow = sO[tp * 4 + pr];
            float* dst = out + (size_t)orow * COUT + tcc * 4;
            red4p(dst,      acc[pr][0], acc[pr][1]);
            red4p(dst + 32, acc[pr][2], acc[pr][3]);
        }
    }
#endif
}

extern "C" void kernel_launch(void* const* d_in, const int* in_sizes, int n_in,
                              void* d_out, int out_size) {
    const float* in_feats = (const float*)d_in[0];   // [N, CIN] f32
    const float* kernel   = (const float*)d_in[1];   // [KVOL, CIN, COUT] f32
    const float* bias     = (const float*)d_in[2];   // [COUT] f32
    const int*   imap     = (const int*)d_in[3];     // [KVOL, P] i32
    const int*   omap     = (const int*)d_in[4];     // [KVOL, P] i32
    float* out = (float*)d_out;                      // [N, COUT] f32

    cudaFuncSetAttribute(conv_main_kernel,
                         cudaFuncAttributeMaxDynamicSharedMemorySize, SMEM_DYN);

    prep_wt_kernel<<<KVOL, 256>>>(kernel);
    init_bias_kernel<<<(N_VOX * COUT / 4) / 256, 256>>>(out, bias);
    conv_main_kernel<<<GRID, THREADS, SMEM_DYN>>>(in_feats, kernel, imap, omap, out);
}

// round 6
// speedup vs baseline: 1.4380x; 1.1553x over previous
#include <cuda_runtime.h>
#include <cstdint>

#define N_VOX   131072
#define KVOL    27
#define P_PAIRS 65536
#define CIN     64
#define COUT    64
#define TILE_P  128
#define NT_K    (P_PAIRS / TILE_P)          // 512 tiles per kernel offset
#define NT_TOTAL (KVOL * NT_K)              // 13824 tiles
#define GRID    288                         // 2 CTAs/SM (81 KB smem each)
#define CHUNK   (NT_TOTAL / GRID)           // 48 tiles per CTA, exact cover
#define THREADS 256

// ---- arch gate: tcgen05 exists only on the arch-specific (sm_103a) pass ----
#if defined(__CUDA_ARCH__) && (__CUDA_ARCH__ >= 1000) && \
    (defined(__CUDA_ARCH_FEAT_SM103_ALL) || defined(__CUDA_ARCH_FEAT_SM100_ALL) || \
     defined(__CUDA_ARCH_SPECIFIC__))
#define TC_PATH 1
#else
#define TC_PATH 0
#endif

// idesc, kind::tf32: dtype=F32(1)<<4, atype=TF32(2)<<7, btype=TF32(2)<<10,
// N>>3 @bit17, M>>4 @bit24  (validated in R5: rel_err 1.79e-4, correct results)
#define IDESC_TF32 ((1u<<4) | (2u<<7) | (2u<<10) | ((COUT/8)<<17) | ((TILE_P/16)<<24))

// dynamic SMEM layout (offsets from 1024-aligned base)
#define OFF_A0   0        // A buf 0: 128x64 tf32, blocked SW128 (32 KB)
#define OFF_A1   32768    // A buf 1
#define OFF_B    65536    // B: Wt[k] 64x64 tf32, blocked SW128 (16 KB)
#define OFF_O    81920    // sO[2][128]
#define OFF_MBAR 82944    // 2 mbarriers
#define OFF_TPTR 82960    // tmem base ptr
#define SMEM_DYN 84992    // incl. 1KB alignment slack

#define TMEM_COLS 128     // two 64-col D buffers

__device__ float g_Wt[KVOL * CIN * COUT];   // W transposed to [k][co][ci], tf32-rounded

typedef unsigned long long ull;

// ---------- base-arch helpers ----------
static __device__ __forceinline__ uint32_t cvta_smem(const void* p) {
    uint32_t a;
    asm("{ .reg .u64 t; cvta.to.shared.u64 t, %1; cvt.u32.u64 %0, t; }" : "=r"(a) : "l"(p));
    return a;
}
static __device__ __forceinline__ uint32_t tf32_rna(float x) {
    uint32_t r; asm("cvt.rna.tf32.f32 %0, %1;" : "=r"(r) : "f"(x)); return r;
}
static __device__ __forceinline__ void sts128(uint32_t a, uint32_t x, uint32_t y,
                                              uint32_t z, uint32_t w) {
    asm volatile("st.shared.v4.b32 [%0], {%1,%2,%3,%4};"
                 :: "r"(a), "r"(x), "r"(y), "r"(z), "r"(w) : "memory");
}
static __device__ __forceinline__ ull pack_dup(float x) {
    ull r; asm("mov.b64 %0, {%1, %1};" : "=l"(r) : "f"(x)); return r;
}
static __device__ __forceinline__ void fma2(ull& d, ull a, ull b) {
    asm("fma.rn.f32x2 %0, %1, %2, %0;" : "+l"(d) : "l"(a), "l"(b));
}
static __device__ __forceinline__ void red4(float* addr, float a, float b, float c, float d) {
    asm volatile("red.global.add.v4.f32 [%0], {%1,%2,%3,%4};"
                 :: "l"(addr), "f"(a), "f"(b), "f"(c), "f"(d) : "memory");
}
static __device__ __forceinline__ void red4p(float* addr, ull ab, ull cd) {
    float a, b, c, d;
    asm("mov.b64 {%0, %1}, %2;" : "=f"(a), "=f"(b) : "l"(ab));
    asm("mov.b64 {%0, %1}, %2;" : "=f"(c), "=f"(d) : "l"(cd));
    red4(addr, a, b, c, d);
}

#if TC_PATH
// ---------- sm_103a-only helpers (all validated in R5) ----------
static __device__ __forceinline__ bool elect_one() {
    uint32_t p;
    asm volatile("{ .reg .pred p; elect.sync _|p, 0xFFFFFFFF; selp.b32 %0, 1, 0, p; }" : "=r"(p));
    return p != 0;
}
static __device__ __forceinline__ uint64_t make_desc(uint32_t addr) {
    // SW128 (layout=2), version=1 (Blackwell), SBO=64, LBO=1
    return 0x4000404000010000ull | (uint64_t)((addr >> 4) & 0x3FFF);
}
static __device__ __forceinline__ void mbar_init(uint32_t mbar, uint32_t cnt) {
    asm volatile("mbarrier.init.shared.b64 [%0], %1;" :: "r"(mbar), "r"(cnt) : "memory");
}
static __device__ __forceinline__ void mbar_wait(uint32_t mbar, uint32_t phase) {
    uint32_t done;
    asm volatile("{ .reg .pred p;\n"
                 "mbarrier.try_wait.parity.acquire.cta.shared::cta.b64 p, [%1], %2;\n"
                 "selp.b32 %0, 1, 0, p; }"
                 : "=r"(done) : "r"(mbar), "r"(phase) : "memory");
    while (!done) {
        asm volatile("{ .reg .pred p;\n"
                     "mbarrier.try_wait.parity.acquire.cta.shared::cta.b64 p, [%1], %2, 0x989680;\n"
                     "selp.b32 %0, 1, 0, p; }"
                     : "=r"(done) : "r"(mbar), "r"(phase) : "memory");
    }
}
static __device__ __forceinline__ void mma_tf32_ss(uint32_t d_tmem, uint64_t ad, uint64_t bd,
                                                   uint32_t idesc, bool acc) {
    uint32_t en = acc ? 1u : 0u;
    asm volatile("{ .reg .pred p; setp.ne.u32 p, %4, 0;\n"
                 "tcgen05.mma.cta_group::1.kind::tf32 [%0], %1, %2, %3, {%5,%5,%5,%5}, p; }"
                 :: "r"(d_tmem), "l"(ad), "l"(bd), "r"(idesc), "r"(en), "r"(0u) : "memory");
}
static __device__ __forceinline__ void tc_commit(uint32_t mbar) {
    asm volatile("tcgen05.commit.cta_group::1.mbarrier::arrive::one.shared::cluster.b64 [%0];"
                 :: "r"(mbar) : "memory");
}
static __device__ __forceinline__ void ldtm32(uint32_t* r, uint32_t taddr) {
    asm volatile("tcgen05.ld.sync.aligned.32x32b.x32.b32 "
                 "{%0,%1,%2,%3,%4,%5,%6,%7,%8,%9,%10,%11,%12,%13,%14,%15,"
                 "%16,%17,%18,%19,%20,%21,%22,%23,%24,%25,%26,%27,%28,%29,%30,%31}, [%32];"
                 : "=r"(r[0]),  "=r"(r[1]),  "=r"(r[2]),  "=r"(r[3]),
                   "=r"(r[4]),  "=r"(r[5]),  "=r"(r[6]),  "=r"(r[7]),
                   "=r"(r[8]),  "=r"(r[9]),  "=r"(r[10]), "=r"(r[11]),
                   "=r"(r[12]), "=r"(r[13]), "=r"(r[14]), "=r"(r[15]),
                   "=r"(r[16]), "=r"(r[17]), "=r"(r[18]), "=r"(r[19]),
                   "=r"(r[20]), "=r"(r[21]), "=r"(r[22]), "=r"(r[23]),
                   "=r"(r[24]), "=r"(r[25]), "=r"(r[26]), "=r"(r[27]),
                   "=r"(r[28]), "=r"(r[29]), "=r"(r[30]), "=r"(r[31])
                 : "r"(taddr));
}
// wait tile j's MMA, LDTM its D buffer, vector scatter-add (R5-validated sequence)
static __device__ __forceinline__ void consume_tile(
    int j, uint32_t base, uint32_t tmem, int colhalf, int rowgrp, int lane,
    const int* sO, float* out)
{
    const int pb = j & 1;
    mbar_wait(base + OFF_MBAR + pb * 8, (uint32_t)((j >> 1) & 1));
    asm volatile("tcgen05.fence::after_thread_sync;" ::: "memory");
    uint32_t r[32];
    ldtm32(r, tmem + pb * COUT + colhalf * 32);
    asm volatile("tcgen05.wait::ld.sync.aligned;" ::: "memory");
    asm volatile("tcgen05.fence::before_thread_sync;" ::: "memory");
    int orow = sO[pb * TILE_P + rowgrp * 32 + lane];
    float* dst = out + (size_t)orow * COUT + colhalf * 32;
    #pragma unroll
    for (int q = 0; q < 8; ++q)
        red4(dst + q * 4,
             __uint_as_float(r[4*q+0]), __uint_as_float(r[4*q+1]),
             __uint_as_float(r[4*q+2]), __uint_as_float(r[4*q+3]));
}
#endif  // TC_PATH

// ---------- prep: Wt[k][co][ci] = tf32(W[k][ci][co]) ----------
__global__ void prep_wt_kernel(const float* __restrict__ W) {
    int k = blockIdx.x;
    const float* Wk = W + (size_t)k * CIN * COUT;
    float* Dk = g_Wt + (size_t)k * CIN * COUT;
    for (int idx = threadIdx.x; idx < CIN * COUT; idx += blockDim.x) {
        int co = idx >> 6, ci = idx & 63;
        Dk[idx] = __uint_as_float(tf32_rna(Wk[ci * COUT + co]));
    }
}

// ---------- out[n][c] = bias[c] ----------
__global__ void init_bias_kernel(float* __restrict__ out, const float* __restrict__ bias) {
    int idx = blockIdx.x * blockDim.x + threadIdx.x;
    int c4  = idx & (COUT / 4 - 1);
    float4 b = reinterpret_cast<const float4*>(bias)[c4];
    reinterpret_cast<float4*>(out)[idx] = b;
}

// ---------- main ----------
extern __shared__ char dynsmem[];

__global__ void __launch_bounds__(THREADS, 2) __cluster_dims__(1, 1, 1)
conv_main_kernel(const float* __restrict__ in_feats,
                 const float* __restrict__ W,
                 const int*   __restrict__ imap,
                 const int*   __restrict__ omap,
                 float*       __restrict__ out)
{
    const int tid = threadIdx.x;
    const int t0  = blockIdx.x * CHUNK;
    const int t1  = t0 + CHUNK;

#if TC_PATH
    // ======== tcgen05 tf32 path, double-buffered pipeline ========
    const uint32_t raw  = cvta_smem(dynsmem);
    const uint32_t base = (raw + 1023u) & ~1023u;
    const int wid  = tid >> 5;
    const int lane = tid & 31;

    if (wid == 0) {
        asm volatile("tcgen05.alloc.cta_group::1.sync.aligned.shared::cta.b32 [%0], %1;"
                     :: "r"(base + OFF_TPTR), "r"((uint32_t)TMEM_COLS) : "memory");
        asm volatile("tcgen05.relinquish_alloc_permit.cta_group::1.sync.aligned;");
    }
    if (tid == 0) {
        mbar_init(base + OFF_MBAR,     1);
        mbar_init(base + OFF_MBAR + 8, 1);
    }
    __syncthreads();
    uint32_t tmem;
    asm volatile("ld.shared.b32 %0, [%1];" : "=r"(tmem) : "r"(base + OFF_TPTR));

    // gather geometry: thread handles row p = tid>>1, ci half h = tid&1
    const int p = tid >> 1, h = tid & 1;
    const uint32_t sa_off = ((((uint32_t)(p >> 3)) + h * 16u) << 10) + ((p & 7) << 7);
    const uint32_t sa_xor = (p & 7) << 4;
    int* sO = reinterpret_cast<int*>(dynsmem + (base - raw) + OFF_O);
    const uint64_t bdesc = make_desc(base + OFF_B);
    const int colhalf = wid >> 2;   // 32-col half of D this warp handles
    const int rowgrp  = wid & 3;    // TMEM subpartition -> output-row group

    int kcur = -1, last = -1, i = 0;
    for (int t = t0; t < t1; ++t, ++i) {
        const int kk = t >> 9;                 // NT_K == 512
        const int ti = t & (NT_K - 1);
        const int b  = i & 1;

        // k change: drain in-flight MMA (tile i-1), then restage B
        if (kk != kcur) {
            if (i > 0 && last < i - 1) {
                consume_tile(i - 1, base, tmem, colhalf, rowgrp, lane, sO, out);
                last = i - 1;
            }
            __syncthreads();
            if (tid < 128) {
                int co = tid >> 1, bh = tid & 1;
                const float4* src = reinterpret_cast<const float4*>(
                    g_Wt + (size_t)kk * CIN * COUT + co * CIN + bh * 32);
                uint32_t sb = base + OFF_B +
                              ((((uint32_t)(co >> 3)) + bh * 8u) << 10) + ((co & 7) << 7);
                uint32_t xo = (co & 7) << 4;
                #pragma unroll
                for (int q = 0; q < 8; ++q) {
                    float4 v = src[q];
                    sts128(sb + ((q * 16) ^ xo),
                           __float_as_uint(v.x), __float_as_uint(v.y),
                           __float_as_uint(v.z), __float_as_uint(v.w));
                }
            }
            kcur = kk;
        }

        // ---- gather tile i -> sA[b] (tf32, blocked SW128); A[b] free: tile i-2 consumed ----
        {
            const size_t mo = (size_t)kk * P_PAIRS + (size_t)ti * TILE_P;
            int row = __ldg(imap + mo + p);
            const float4* src = reinterpret_cast<const float4*>(
                in_feats + (size_t)row * CIN + h * 32);
            uint32_t sa = base + (b ? OFF_A1 : OFF_A0) + sa_off;
            #pragma unroll
            for (int q = 0; q < 8; ++q) {
                float4 v = src[q];
                sts128(sa + ((q * 16) ^ sa_xor),
                       tf32_rna(v.x), tf32_rna(v.y), tf32_rna(v.z), tf32_rna(v.w));
            }
            if (tid < TILE_P) sO[b * TILE_P + tid] = __ldg(omap + mo + tid);
        }
        asm volatile("fence.proxy.async.shared::cta;" ::: "memory");
        __syncthreads();

        // ---- issue 8 MMA k-steps for tile i into D[b] (async) ----
        if (wid == 0) {
            asm volatile("tcgen05.fence::after_thread_sync;" ::: "memory");
            if (elect_one()) {
                uint64_t adesc = make_desc(base + (b ? OFF_A1 : OFF_A0));
                #pragma unroll
                for (int s = 0; s < 8; ++s)
                    mma_tf32_ss(tmem + b * COUT,
                                adesc + (uint64_t)((s >> 2) * 1024 + (s & 3) * 2),
                                bdesc + (uint64_t)((s >> 2) * 512  + (s & 3) * 2),
                                IDESC_TF32, s > 0);
                tc_commit(base + OFF_MBAR + b * 8);
            }
        }

        // ---- consume tile i-1 while tile i's MMA runs ----
        if (i > 0 && last < i - 1) {
            consume_tile(i - 1, base, tmem, colhalf, rowgrp, lane, sO, out);
            last = i - 1;
        }
        __syncthreads();   // sO/A buffer reuse boundary (MMA of tile i stays in flight)
    }
    // drain final tile
    if (last < i - 1)
        consume_tile(i - 1, base, tmem, colhalf, rowgrp, lane, sO, out);

    __syncthreads();
    if (wid == 0) {
        asm volatile("tcgen05.dealloc.cta_group::1.sync.aligned.b32 %0, %1;"
                     :: "r"(tmem), "r"((uint32_t)TMEM_COLS));
    }

#else
    // ======== base-arch fallback: f32x2 register GEMM (R1-proven logic) ========
    float* sW = reinterpret_cast<float*>(dynsmem);            // [64][64]
    float* sX = reinterpret_cast<float*>(dynsmem + 16384);    // [64][128]
    int*   sO = reinterpret_cast<int*>(dynsmem + 49152);      // [128]
    const int tp = tid >> 3, tcc = tid & 7, gp = tid >> 1, gh = tid & 1;

    int kcur = -1;
    for (int t = t0; t < t1; ++t) {
        const int kk = t >> 9;
        const int ti = t & (NT_K - 1);
        __syncthreads();
        if (kk != kcur) {
            const float4* Wk = reinterpret_cast<const float4*>(W + (size_t)kk * CIN * COUT);
            for (int idx = tid; idx < CIN * COUT / 4; idx += THREADS)
                reinterpret_cast<float4*>(sW)[idx] = Wk[idx];
            kcur = kk;
        }
        {
            const size_t mo = (size_t)kk * P_PAIRS + (size_t)ti * TILE_P;
            int row = __ldg(imap + mo + gp);
            const float4* src = reinterpret_cast<const float4*>(
                in_feats + (size_t)row * CIN + gh * 32);
            #pragma unroll
            for (int q = 0; q < 8; ++q) {
                float4 v = src[q];
                int ci = gh * 32 + q * 4;
                sX[(ci + 0) * TILE_P + gp] = v.x;
                sX[(ci + 1) * TILE_P + gp] = v.y;
                sX[(ci + 2) * TILE_P + gp] = v.z;
                sX[(ci + 3) * TILE_P + gp] = v.w;
            }
            if (tid < TILE_P) sO[tid] = __ldg(omap + mo + tid);
        }
        __syncthreads();

        ull acc[4][4];
        #pragma unroll
        for (int a = 0; a < 4; ++a)
            #pragma unroll
            for (int c = 0; c < 4; ++c) acc[a][c] = 0ull;

        #pragma unroll 4
        for (int ci = 0; ci < CIN; ++ci) {
            float4 xv = *reinterpret_cast<const float4*>(&sX[ci * TILE_P + tp * 4]);
            ulonglong2 wa = *reinterpret_cast<const ulonglong2*>(&sW[ci * COUT + tcc * 4]);
            ulonglong2 wb = *reinterpret_cast<const ulonglong2*>(&sW[ci * COUT + 32 + tcc * 4]);
            ull x0 = pack_dup(xv.x), x1 = pack_dup(xv.y);
            ull x2 = pack_dup(xv.z), x3 = pack_dup(xv.w);
            fma2(acc[0][0], x0, wa.x); fma2(acc[0][1], x0, wa.y);
            fma2(acc[0][2], x0, wb.x); fma2(acc[0][3], x0, wb.y);
            fma2(acc[1][0], x1, wa.x); fma2(acc[1][1], x1, wa.y);
            fma2(acc[1][2], x1, wb.x); fma2(acc[1][3], x1, wb.y);
            fma2(acc[2][0], x2, wa.x); fma2(acc[2][1], x2, wa.y);
            fma2(acc[2][2], x2, wb.x); fma2(acc[2][3], x2, wb.y);
            fma2(acc[3][0], x3, wa.x); fma2(acc[3][1], x3, wa.y);
            fma2(acc[3][2], x3, wb.x); fma2(acc[3][3], x3, wb.y);
        }

        #pragma unroll
        for (int pr = 0; pr < 4; ++pr) {
            int orow = sO[tp * 4 + pr];
            float* dst = out + (size_t)orow * COUT + tcc * 4;
            red4p(dst,      acc[pr][0], acc[pr][1]);
            red4p(dst + 32, acc[pr][2], acc[pr][3]);
        }
    }
#endif
}

extern "C" void kernel_launch(void* const* d_in, const int* in_sizes, int n_in,
                              void* d_out, int out_size) {
    const float* in_feats = (const float*)d_in[0];   // [N, CIN] f32
    const float* kernel   = (const float*)d_in[1];   // [KVOL, CIN, COUT] f32
    const float* bias     = (const float*)d_in[2];   // [COUT] f32
    const int*   imap     = (const int*)d_in[3];     // [KVOL, P] i32
    const int*   omap     = (const int*)d_in[4];     // [KVOL, P] i32
    float* out = (float*)d_out;                      // [N, COUT] f32

    cudaFuncSetAttribute(conv_main_kernel,
                         cudaFuncAttributeMaxDynamicSharedMemorySize, SMEM_DYN);

    prep_wt_kernel<<<KVOL, 256>>>(kernel);
    init_bias_kernel<<<(N_VOX * COUT / 4) / 256, 256>>>(out, bias);
    conv_main_kernel<<<GRID, THREADS, SMEM_DYN>>>(in_feats, kernel, imap, omap, out);
}